// round 15
// baseline (speedup 1.0000x reference)
#include <cuda_runtime.h>
#include <cuda_bf16.h>
#include <cstdint>
#include <math.h>

#define NN 20000
#define NE 320000
#define NG 256
#define DD 128
#define NL 4
#define AVG_LOG 2.8332133440562162f
#define EPSV 1e-5f
#define SLOPE 0.01f

#define KA 1664            // A row length (bf16) = h(128) + 3*4*128
#define WL 262144          // weight plane bf16 per layer
#define WOFF_POST 32768
#define WOFF_MIX 245760

// ---------------- scratch (static device memory; no allocation) ----------------
__device__ float g_h[NN * DD];
__device__ float g_P1[NN * DD];
__device__ float g_P2[NN * DD];
__device__ float g_phs[NN * DD];
__device__ float g_bond[4 * DD];
__device__ __nv_bfloat16 g_AsH[(size_t)NN * KA];
__device__ __nv_bfloat16 g_AsL[(size_t)NN * KA];
__device__ __nv_bfloat16 g_phsH[(size_t)NN * DD];
__device__ __nv_bfloat16 g_phsL[(size_t)NN * DD];
__device__ __nv_bfloat16 g_WsH[4 * WL];
__device__ __nv_bfloat16 g_WsL[4 * WL];
__device__ int   g_deg[NN];
__device__ int   g_off[NN + 1];
__device__ int   g_cur[NN];
__device__ int2  g_epack[NE];
__device__ float g_dinv[NN], g_amp[NN], g_att[NN];
__device__ float g_bnsum[DD], g_bnsq[DD];
__device__ float g_gsum[NG * DD];
__device__ float g_gcnt[NG];

// ---------------- helpers ----------------
__device__ __forceinline__ void splitp(float x, float y, __nv_bfloat162& h, __nv_bfloat162& l) {
    __nv_bfloat16 hx = __float2bfloat16_rn(x);
    __nv_bfloat16 hy = __float2bfloat16_rn(y);
    h.x = hx; h.y = hy;
    l.x = __float2bfloat16_rn(x - __bfloat162float(hx));
    l.y = __float2bfloat16_rn(y - __bfloat162float(hy));
}

__device__ __forceinline__ void mma_bf16(float c[4], const uint32_t a[4], const uint32_t b[2]) {
    asm volatile(
        "mma.sync.aligned.m16n8k16.row.col.f32.bf16.bf16.f32 "
        "{%0,%1,%2,%3}, {%4,%5,%6,%7}, {%8,%9}, {%0,%1,%2,%3};"
        : "+f"(c[0]), "+f"(c[1]), "+f"(c[2]), "+f"(c[3])
        : "r"(a[0]), "r"(a[1]), "r"(a[2]), "r"(a[3]), "r"(b[0]), "r"(b[1]));
}

__device__ __forceinline__ void cpa16(void* dst, const void* src, bool pred) {
    uint32_t d = (uint32_t)__cvta_generic_to_shared(dst);
    int sz = pred ? 16 : 0;
    asm volatile("cp.async.cg.shared.global [%0], [%1], 16, %2;" :: "r"(d), "l"(src), "r"(sz));
}

#define LDSM4(r, addr)                                                          \
    asm volatile("ldmatrix.sync.aligned.m8n8.x4.shared.b16 {%0,%1,%2,%3}, [%4];"\
        : "=r"((r)[0]), "=r"((r)[1]), "=r"((r)[2]), "=r"((r)[3]) : "r"(addr))

#define LDSM4T(r, addr)                                                         \
    asm volatile("ldmatrix.sync.aligned.m8n8.x4.trans.shared.b16 {%0,%1,%2,%3}, [%4];"\
        : "=r"((r)[0]), "=r"((r)[1]), "=r"((r)[2]), "=r"((r)[3]) : "r"(addr))

// ---------------- weight pre-split (once per launch) ----------------
__global__ void k_wsplit(const float* __restrict__ preW, const float* __restrict__ postW,
                         const float* __restrict__ mixW) {
    int idx2 = blockIdx.x * 256 + threadIdx.x;   // 0..524287 (element pairs)
    int l = idx2 >> 17;
    int rem2 = (idx2 & 131071) * 2;
    const float* src;
    if (rem2 < WOFF_POST) {
        int k = rem2 >> 8, n = rem2 & 255;
        src = preW + (size_t)l * 384 * 128 + (size_t)((n < 128 ? k : 128 + k)) * 128 + (n & 127);
    } else if (rem2 < WOFF_MIX) {
        int r2 = rem2 - WOFF_POST;
        src = postW + (size_t)l * 1664 * 128 + (size_t)(r2 >> 7) * 128 + (r2 & 127);
    } else {
        int r2 = rem2 - WOFF_MIX;
        src = mixW + (size_t)l * 128 * 128 + (size_t)(r2 >> 7) * 128 + (r2 & 127);
    }
    float a = src[0], b = src[1];
    __nv_bfloat162 h, lo;
    splitp(a, b, h, lo);
    *(__nv_bfloat162*)&g_WsH[(size_t)l * WL + rem2] = h;
    *(__nv_bfloat162*)&g_WsL[(size_t)l * WL + rem2] = lo;
}

// ---------------- setup kernels ----------------
__global__ void k_init_zero() {
    int i = blockIdx.x * blockDim.x + threadIdx.x;
    if (i < NN) { g_deg[i] = 0; g_cur[i] = 0; }
}

__global__ void k_count(const int* __restrict__ dst) {
    int e = blockIdx.x * blockDim.x + threadIdx.x;
    if (e < NE) atomicAdd(&g_deg[dst[e]], 1);
}

__global__ void k_scan() {
    __shared__ int s[1024];
    __shared__ int run;
    int t = threadIdx.x;
    if (t == 0) run = 0;
    for (int base = 0; base < NN; base += 1024) {
        __syncthreads();
        int r = run;
        int v = (base + t < NN) ? g_deg[base + t] : 0;
        s[t] = v;
        __syncthreads();
        for (int d2 = 1; d2 < 1024; d2 <<= 1) {
            int tv = (t >= d2) ? s[t - d2] : 0;
            __syncthreads();
            s[t] += tv;
            __syncthreads();
        }
        if (base + t < NN) g_off[base + t] = r + s[t] - v;
        if (t == 0) run = r + s[1023];
    }
    __syncthreads();
    if (t == 0) g_off[NN] = run;
}

__global__ void k_nodeprep() {
    int n = blockIdx.x * blockDim.x + threadIdx.x;
    if (n >= NN) return;
    float d = (float)g_deg[n];
    g_dinv[n] = 1.0f / fmaxf(d, 1.0f);
    float logd = log1pf(d);
    g_amp[n] = logd / AVG_LOG;
    g_att[n] = AVG_LOG / fmaxf(logd, EPSV);
}

__global__ void k_scatter(const int* __restrict__ src, const int* __restrict__ dst,
                          const int* __restrict__ attr) {
    int e = blockIdx.x * blockDim.x + threadIdx.x;
    if (e >= NE) return;
    int d = dst[e];
    int pos = g_off[d] + atomicAdd(&g_cur[d], 1);
    g_epack[pos] = make_int2(src[e], attr[e]);
}

__global__ void k_embed(const int* __restrict__ x, const float* __restrict__ atom_emb) {
    int idx = blockIdx.x * blockDim.x + threadIdx.x;
    if (idx >= NN * 64) return;
    int n = idx >> 6, c = (idx & 63) * 2;
    const float* e = &atom_emb[x[n] * DD];
    float a = e[c], b = e[c + 1];
    g_h[n * DD + c] = a;
    g_h[n * DD + c + 1] = b;
    __nv_bfloat162 h, lo;
    splitp(a, b, h, lo);
    *(__nv_bfloat162*)&g_AsH[(size_t)n * KA + c] = h;
    *(__nv_bfloat162*)&g_AsL[(size_t)n * KA + c] = lo;
}

__global__ void k_bond(const float* __restrict__ bond_emb, const float* __restrict__ preWl,
                       const float* __restrict__ preBl) {
    int t = threadIdx.x;            // 512 threads
    if (t < DD) { g_bnsum[t] = 0.f; g_bnsq[t] = 0.f; }
    int b = t >> 7, c = t & 127;
    float a = preBl[c];
    for (int k = 0; k < DD; k++)
        a += bond_emb[b * DD + k] * preWl[(256 + k) * DD + c];
    g_bond[t] = a;
}

// ---------------- bf16-split GEMM: ldmatrix + 3-stage cp.async, templated BN ----------------
// C[M,*] = epi(A[M,K] @ B[K,*]); A,B as hi/lo bf16 planes.
// NB=128 (pre): grid.y selects weight half (ldb=256), outputs local cols to C/C2.
// NB=64 (post/mix): grid.y selects n-half of B (ldb=128), outputs global cols.
// EPI 0: fp32. EPI 1: +bias leaky -> split planes. EPI 2: +bias leaky *snorm -> fp32 + BN sums.
// BM=64, BK=32. 8 warps; NB=128: 2x4 warps (tile 32x32); NB=64: 4x2 warps (tile 16x32).

#define APITCH 72
#define SA_PL (64 * APITCH)
#define NSTG 3

template <int EPI, int NB>
__global__ void __launch_bounds__(256, 2) tgemm(const __nv_bfloat16* __restrict__ AH,
                                                const __nv_bfloat16* __restrict__ AL, int lda,
                                                const __nv_bfloat16* __restrict__ BH,
                                                const __nv_bfloat16* __restrict__ BL, int ldb,
                                                const float* __restrict__ bias,
                                                float* __restrict__ C, float* __restrict__ C2,
                                                __nv_bfloat16* __restrict__ CsH,
                                                __nv_bfloat16* __restrict__ CsL,
                                                int M, int K,
                                                const float* __restrict__ snorm) {
    constexpr int BPITCH = NB + 8;
    constexpr int SB_PL = 32 * BPITCH;
    constexpr int STG = 2 * SA_PL + 2 * SB_PL;
    constexpr int CHR = NB / 8;        // B chunk-loads per row per plane
    constexpr int BITER = CHR / 4;     // B copy iterations (4 or 2)
    constexpr int WN = NB / 32;        // warps along n
    constexpr int WM = 8 / WN;         // warps along m
    constexpr int MF = 4 / WM;         // m-fragments per warp

    extern __shared__ __nv_bfloat16 sm[];
    __shared__ float bnS[128], bnQ[128];

    int tid = threadIdx.x;
    int lane = tid & 31, wid = tid >> 5;
    int wm = wid % WM, wn = wid / WM;
    int g = lane >> 2, tg = lane & 3;
    int mat = lane >> 3, l8 = lane & 7;
    int m0 = wm * (16 * MF), n0 = wn * 32;
    int row0 = blockIdx.x * 64;
    int bcol = blockIdx.y * NB;
    float* Cout = (EPI == 0 && blockIdx.y) ? C2 : C;
    int obase = (EPI == 0) ? 0 : bcol;

    if (EPI == 2 && tid < 128) { bnS[tid] = 0.f; bnQ[tid] = 0.f; }

    float acc[MF][4][4];
#pragma unroll
    for (int i = 0; i < MF; i++)
#pragma unroll
        for (int j = 0; j < 4; j++)
#pragma unroll
            for (int q = 0; q < 4; q++) acc[i][j][q] = 0.f;

#define COPY_TILE(K0, BUF)                                                      \
    {                                                                           \
        __nv_bfloat16* stg = sm + (BUF) * STG;                                  \
        _Pragma("unroll")                                                       \
        for (int i = 0; i < 2; i++) {                                           \
            int j = tid + i * 256;                                              \
            int p = j >> 8, r2 = j & 255;                                       \
            int row = r2 >> 2, ch = (r2 & 3) * 8;                               \
            int gr = row0 + row;                                                \
            int gc = gr < M ? gr : M - 1;                                       \
            const __nv_bfloat16* s = (p ? AL : AH) + (size_t)gc * lda + (K0) + ch; \
            cpa16(stg + p * SA_PL + row * APITCH + ch, s, gr < M);              \
        }                                                                       \
        _Pragma("unroll")                                                       \
        for (int i = 0; i < BITER; i++) {                                       \
            int j = tid + i * 256;                                              \
            int p = j / (32 * CHR), r2 = j % (32 * CHR);                        \
            int kr = r2 / CHR, ch = (r2 % CHR) * 8;                             \
            const __nv_bfloat16* s = (p ? BL : BH) + (size_t)((K0) + kr) * ldb + bcol + ch; \
            cpa16(stg + 2 * SA_PL + p * SB_PL + kr * BPITCH + ch, s, true);     \
        }                                                                       \
        asm volatile("cp.async.commit_group;");                                 \
    }

    int T = K >> 5;
    COPY_TILE(0, 0);
    if (T > 1) { COPY_TILE(32, 1); }
    else { asm volatile("cp.async.commit_group;"); }

    int buf = 0;
    for (int t = 0; t < T; t++) {
        asm volatile("cp.async.wait_group 1;");
        __syncthreads();
        if (t + 2 < T) { COPY_TILE((t + 2) * 32, (t + 2) % NSTG); }
        else { asm volatile("cp.async.commit_group;"); }

        __nv_bfloat16* sAH = sm + buf * STG;
        __nv_bfloat16* sAL = sAH + SA_PL;
        __nv_bfloat16* sBH = sAH + 2 * SA_PL;
        __nv_bfloat16* sBL = sBH + SB_PL;
        buf = (buf + 1 == NSTG) ? 0 : buf + 1;

#pragma unroll
        for (int ks = 0; ks < 2; ks++) {
            int kb = ks * 16;
            uint32_t ah[MF][4], al[MF][4], bh[2][4], bl[2][4];
#pragma unroll
            for (int mf = 0; mf < MF; mf++) {
                int off = (m0 + mf * 16 + (mat & 1) * 8 + l8) * APITCH + kb + (mat >> 1) * 8;
                uint32_t aH = (uint32_t)__cvta_generic_to_shared(sAH + off);
                uint32_t aL = (uint32_t)__cvta_generic_to_shared(sAL + off);
                LDSM4(ah[mf], aH);
                LDSM4(al[mf], aL);
            }
#pragma unroll
            for (int np = 0; np < 2; np++) {
                int off = (kb + (mat & 1) * 8 + l8) * BPITCH + n0 + np * 16 + (mat >> 1) * 8;
                uint32_t bHa = (uint32_t)__cvta_generic_to_shared(sBH + off);
                uint32_t bLa = (uint32_t)__cvta_generic_to_shared(sBL + off);
                LDSM4T(bh[np], bHa);
                LDSM4T(bl[np], bLa);
            }
#pragma unroll
            for (int mf = 0; mf < MF; mf++)
#pragma unroll
                for (int nf = 0; nf < 4; nf++) {
                    uint32_t bhf[2] = {bh[nf >> 1][(nf & 1) * 2], bh[nf >> 1][(nf & 1) * 2 + 1]};
                    uint32_t blf[2] = {bl[nf >> 1][(nf & 1) * 2], bl[nf >> 1][(nf & 1) * 2 + 1]};
                    mma_bf16(acc[mf][nf], ah[mf], bhf);
                    mma_bf16(acc[mf][nf], ah[mf], blf);
                    mma_bf16(acc[mf][nf], al[mf], bhf);
                }
        }
        __syncthreads();
    }

    // ---- epilogue ----
#pragma unroll
    for (int mf = 0; mf < MF; mf++) {
        int r0 = row0 + m0 + mf * 16 + g;
        int r1 = r0 + 8;
        float sn0 = 1.f, sn1 = 1.f;
        if (EPI == 2) {
            if (r0 < M) sn0 = snorm[r0];
            if (r1 < M) sn1 = snorm[r1];
        }
#pragma unroll
        for (int nf = 0; nf < 4; nf++) {
            int gcol = obase + n0 + nf * 8 + 2 * tg;
            float b0 = 0.f, b1 = 0.f;
            if (EPI >= 1) { b0 = bias[gcol]; b1 = bias[gcol + 1]; }
            float v0 = acc[mf][nf][0], v1 = acc[mf][nf][1];
            float v2 = acc[mf][nf][2], v3 = acc[mf][nf][3];
            if (EPI >= 1) {
                v0 += b0; v0 = v0 > 0.f ? v0 : SLOPE * v0;
                v1 += b1; v1 = v1 > 0.f ? v1 : SLOPE * v1;
                v2 += b0; v2 = v2 > 0.f ? v2 : SLOPE * v2;
                v3 += b1; v3 = v3 > 0.f ? v3 : SLOPE * v3;
            }
            if (EPI == 1) {
                __nv_bfloat162 h, lo;
                if (r0 < M) {
                    splitp(v0, v1, h, lo);
                    *(__nv_bfloat162*)&CsH[(size_t)r0 * DD + gcol] = h;
                    *(__nv_bfloat162*)&CsL[(size_t)r0 * DD + gcol] = lo;
                }
                if (r1 < M) {
                    splitp(v2, v3, h, lo);
                    *(__nv_bfloat162*)&CsH[(size_t)r1 * DD + gcol] = h;
                    *(__nv_bfloat162*)&CsL[(size_t)r1 * DD + gcol] = lo;
                }
            } else {
                if (EPI == 2) { v0 *= sn0; v1 *= sn0; v2 *= sn1; v3 *= sn1; }
                if (r0 < M) *(float2*)&Cout[(size_t)r0 * DD + gcol] = make_float2(v0, v1);
                if (r1 < M) *(float2*)&Cout[(size_t)r1 * DD + gcol] = make_float2(v2, v3);
                if (EPI == 2) {
                    float a0 = (r0 < M) ? v0 : 0.f, a1 = (r0 < M) ? v1 : 0.f;
                    float a2 = (r1 < M) ? v2 : 0.f, a3 = (r1 < M) ? v3 : 0.f;
                    float s0 = a0 + a2, s1 = a1 + a3;
                    float q0 = a0 * a0 + a2 * a2, q1 = a1 * a1 + a3 * a3;
#pragma unroll
                    for (int o = 4; o <= 16; o <<= 1) {
                        s0 += __shfl_down_sync(0xffffffffu, s0, o);
                        s1 += __shfl_down_sync(0xffffffffu, s1, o);
                        q0 += __shfl_down_sync(0xffffffffu, q0, o);
                        q1 += __shfl_down_sync(0xffffffffu, q1, o);
                    }
                    if (lane < 4) {
                        atomicAdd(&bnS[gcol], s0);
                        atomicAdd(&bnS[gcol + 1], s1);
                        atomicAdd(&bnQ[gcol], q0);
                        atomicAdd(&bnQ[gcol + 1], q1);
                    }
                }
            }
        }
    }
    if (EPI == 2) {
        __syncthreads();
        if (tid < 128) {
            atomicAdd(&g_bnsum[tid], bnS[tid]);
            atomicAdd(&g_bnsq[tid], bnQ[tid]);
        }
    }
}

// ---------------- edge aggregation (CSR, atomic-free, MLP=4) ----------------
__global__ void k_edgeagg() {
    __shared__ __align__(16) float sb[4 * DD];
    int tid = threadIdx.x;
    for (int i = tid; i < 4 * DD; i += blockDim.x) sb[i] = g_bond[i];
    __syncthreads();
    int w = (blockIdx.x * blockDim.x + tid) >> 5;
    int lane = tid & 31;
    int c0 = lane * 4;
    float4 base = *(float4*)&g_P1[w * DD + c0];
    int off = g_off[w], deg = g_deg[w];
    float s0 = 0, s1 = 0, s2 = 0, s3 = 0;
    float q0 = 0, q1 = 0, q2 = 0, q3 = 0;
    float x0 = -3.4e38f, x1 = -3.4e38f, x2 = -3.4e38f, x3 = -3.4e38f;
    float n0 = 3.4e38f, n1 = 3.4e38f, n2 = 3.4e38f, n3 = 3.4e38f;

#define EPROC(p, bb)                                                            \
    {                                                                           \
        float m0 = base.x + (p).x + (bb).x; m0 = m0 > 0 ? m0 : SLOPE * m0;      \
        float m1 = base.y + (p).y + (bb).y; m1 = m1 > 0 ? m1 : SLOPE * m1;      \
        float m2 = base.z + (p).z + (bb).z; m2 = m2 > 0 ? m2 : SLOPE * m2;      \
        float m3 = base.w + (p).w + (bb).w; m3 = m3 > 0 ? m3 : SLOPE * m3;      \
        s0 += m0; s1 += m1; s2 += m2; s3 += m3;                                 \
        q0 += m0 * m0; q1 += m1 * m1; q2 += m2 * m2; q3 += m3 * m3;             \
        x0 = fmaxf(x0, m0); x1 = fmaxf(x1, m1);                                 \
        x2 = fmaxf(x2, m2); x3 = fmaxf(x3, m3);                                 \
        n0 = fminf(n0, m0); n1 = fminf(n1, m1);                                 \
        n2 = fminf(n2, m2); n3 = fminf(n3, m3);                                 \
    }

    int i = 0;
    for (; i + 4 <= deg; i += 4) {
        int e = off + i;
        int2 e0 = g_epack[e], e1 = g_epack[e + 1], e2 = g_epack[e + 2], e3 = g_epack[e + 3];
        float4 p0 = *(float4*)&g_P2[e0.x * DD + c0];
        float4 p1 = *(float4*)&g_P2[e1.x * DD + c0];
        float4 p2 = *(float4*)&g_P2[e2.x * DD + c0];
        float4 p3 = *(float4*)&g_P2[e3.x * DD + c0];
        float4 b0 = *(float4*)&sb[e0.y * DD + c0];
        float4 b1 = *(float4*)&sb[e1.y * DD + c0];
        float4 b2 = *(float4*)&sb[e2.y * DD + c0];
        float4 b3 = *(float4*)&sb[e3.y * DD + c0];
        EPROC(p0, b0); EPROC(p1, b1); EPROC(p2, b2); EPROC(p3, b3);
    }
    for (; i < deg; i++) {
        int2 ep = g_epack[off + i];
        float4 p = *(float4*)&g_P2[ep.x * DD + c0];
        float4 bb = *(float4*)&sb[ep.y * DD + c0];
        EPROC(p, bb);
    }
#undef EPROC

    float dinv = g_dinv[w];
    bool nb = deg > 0;
    float me0 = s0 * dinv, me1 = s1 * dinv, me2 = s2 * dinv, me3 = s3 * dinv;
    float sd0 = nb ? sqrtf(fmaxf(q0 * dinv - me0 * me0, 0.f) + EPSV) : 0.f;
    float sd1 = nb ? sqrtf(fmaxf(q1 * dinv - me1 * me1, 0.f) + EPSV) : 0.f;
    float sd2 = nb ? sqrtf(fmaxf(q2 * dinv - me2 * me2, 0.f) + EPSV) : 0.f;
    float sd3 = nb ? sqrtf(fmaxf(q3 * dinv - me3 * me3, 0.f) + EPSV) : 0.f;
    if (!nb) { x0 = x1 = x2 = x3 = 0.f; n0 = n1 = n2 = n3 = 0.f; }

    float vs[4][4] = {{me0, me1, me2, me3}, {x0, x1, x2, x3},
                      {n0, n1, n2, n3}, {sd0, sd1, sd2, sd3}};
    float amp = g_amp[w], att = g_att[w];
    float scs[3] = {1.f, amp, att};
#pragma unroll
    for (int v = 0; v < 3; v++) {
        float sc = scs[v];
#pragma unroll
        for (int s = 0; s < 4; s++) {
            size_t k = (size_t)w * KA + 128 + v * 512 + s * 128 + c0;
            __nv_bfloat162 h, lo;
            splitp(sc * vs[s][0], sc * vs[s][1], h, lo);
            *(__nv_bfloat162*)&g_AsH[k] = h;
            *(__nv_bfloat162*)&g_AsL[k] = lo;
            splitp(sc * vs[s][2], sc * vs[s][3], h, lo);
            *(__nv_bfloat162*)&g_AsH[k + 2] = h;
            *(__nv_bfloat162*)&g_AsL[k + 2] = lo;
        }
    }
}

// ---------------- batchnorm residual ----------------
__global__ void k_bnres(const float* __restrict__ gamma, const float* __restrict__ beta) {
    int idx = blockIdx.x * blockDim.x + threadIdx.x;
    if (idx >= NN * 64) return;
    int n = idx >> 6, c = (idx & 63) * 2;
    float mu0 = g_bnsum[c] * (1.0f / NN);
    float var0 = g_bnsq[c] * (1.0f / NN) - mu0 * mu0;
    float mu1 = g_bnsum[c + 1] * (1.0f / NN);
    float var1 = g_bnsq[c + 1] * (1.0f / NN) - mu1 * mu1;
    float p0 = g_phs[n * DD + c], p1 = g_phs[n * DD + c + 1];
    float h0 = g_h[n * DD + c] + gamma[c] * (p0 - mu0) * rsqrtf(var0 + EPSV) + beta[c];
    float h1 = g_h[n * DD + c + 1] + gamma[c + 1] * (p1 - mu1) * rsqrtf(var1 + EPSV) + beta[c + 1];
    g_h[n * DD + c] = h0;
    g_h[n * DD + c + 1] = h1;
    __nv_bfloat162 h, lo;
    splitp(h0, h1, h, lo);
    *(__nv_bfloat162*)&g_AsH[(size_t)n * KA + c] = h;
    *(__nv_bfloat162*)&g_AsL[(size_t)n * KA + c] = lo;
}

// ---------------- pooling + readout ----------------
__global__ void k_zero_pool() {
    int i = blockIdx.x * blockDim.x + threadIdx.x;
    if (i < NG * DD) g_gsum[i] = 0.f;
    if (i < NG) g_gcnt[i] = 0.f;
}

__global__ void k_pool(const int* __restrict__ batch) {
    int idx = blockIdx.x * blockDim.x + threadIdx.x;
    if (idx >= NN * 32) return;
    int n = idx >> 5, q = idx & 31;
    int b = batch[n];
    float4 v = *(float4*)&g_h[n * DD + q * 4];
    atomicAdd(&g_gsum[b * DD + q * 4 + 0], v.x);
    atomicAdd(&g_gsum[b * DD + q * 4 + 1], v.y);
    atomicAdd(&g_gsum[b * DD + q * 4 + 2], v.z);
    atomicAdd(&g_gsum[b * DD + q * 4 + 3], v.w);
    if (q == 0) atomicAdd(&g_gcnt[b], 1.f);
}

__global__ void k_readout(const float* __restrict__ rW1, const float* __restrict__ rb1,
                          const float* __restrict__ rW2, const float* __restrict__ rb2,
                          const float* __restrict__ rW3, const float* __restrict__ rb3,
                          float* __restrict__ out) {
    __shared__ float sg[128], s1[64], s2[32];
    int b = blockIdx.x, t = threadIdx.x;   // 64 threads
    float cnt = fmaxf(g_gcnt[b], 1.f);
    for (int i = t; i < 128; i += 64) sg[i] = g_gsum[b * DD + i] / cnt;
    __syncthreads();
    float a = 0.f;
    for (int k = 0; k < 128; k++) a += sg[k] * rW1[k * 64 + t];
    s1[t] = fmaxf(a + rb1[t], 0.f);
    __syncthreads();
    if (t < 32) {
        float a2 = 0.f;
        for (int k = 0; k < 64; k++) a2 += s1[k] * rW2[k * 32 + t];
        s2[t] = fmaxf(a2 + rb2[t], 0.f);
    }
    __syncthreads();
    if (t < 32) {
        float p = s2[t] * rW3[t];
#pragma unroll
        for (int o = 16; o; o >>= 1) p += __shfl_down_sync(0xffffffffu, p, o);
        if (t == 0) out[b] = p + rb3[0];
    }
}

// ---------------- host launcher ----------------
static void* symp(const void* sym) {
    void* p = nullptr;
    cudaGetSymbolAddress(&p, sym);
    return p;
}

#define SMEM128 (NSTG * (2 * SA_PL + 2 * 32 * 136) * 2)   // 107520
#define SMEM64  (NSTG * (2 * SA_PL + 2 * 32 * 72) * 2)    // 82944

extern "C" void kernel_launch(void* const* d_in, const int* in_sizes, int n_in,
                              void* d_out, int out_size) {
    const int* x = (const int*)d_in[0];
    const int* batch = (const int*)d_in[1];
    const int* eidx = (const int*)d_in[2];    // [2,E]: src then dst
    const float* snorm = (const float*)d_in[3];
    const int* eattr = (const int*)d_in[4];
    const float* atom_emb = (const float*)d_in[5];
    const float* bond_emb = (const float*)d_in[6];
    const float* preW = (const float*)d_in[7];   // [4,384,128]
    const float* preB = (const float*)d_in[8];
    const float* postW = (const float*)d_in[9];  // [4,1664,128]
    const float* postB = (const float*)d_in[10];
    const float* mixW = (const float*)d_in[11];  // [4,128,128]
    const float* mixB = (const float*)d_in[12];
    const float* gamma = (const float*)d_in[13];
    const float* beta = (const float*)d_in[14];
    const float* rW1 = (const float*)d_in[15];
    const float* rb1 = (const float*)d_in[16];
    const float* rW2 = (const float*)d_in[17];
    const float* rb2 = (const float*)d_in[18];
    const float* rW3 = (const float*)d_in[19];
    const float* rb3 = (const float*)d_in[20];
    float* out = (float*)d_out;

    float* p_P1 = (float*)symp(g_P1);
    float* p_P2 = (float*)symp(g_P2);
    float* p_phs = (float*)symp(g_phs);
    __nv_bfloat16* p_AsH = (__nv_bfloat16*)symp(g_AsH);
    __nv_bfloat16* p_AsL = (__nv_bfloat16*)symp(g_AsL);
    __nv_bfloat16* p_phsH = (__nv_bfloat16*)symp(g_phsH);
    __nv_bfloat16* p_phsL = (__nv_bfloat16*)symp(g_phsL);
    __nv_bfloat16* p_WsH = (__nv_bfloat16*)symp(g_WsH);
    __nv_bfloat16* p_WsL = (__nv_bfloat16*)symp(g_WsL);

    cudaFuncSetAttribute(tgemm<0, 128>, cudaFuncAttributeMaxDynamicSharedMemorySize, SMEM128);
    cudaFuncSetAttribute(tgemm<1, 64>, cudaFuncAttributeMaxDynamicSharedMemorySize, SMEM64);
    cudaFuncSetAttribute(tgemm<2, 64>, cudaFuncAttributeMaxDynamicSharedMemorySize, SMEM64);

    const int src_off = 0, dst_off = NE;
    const int GB = (NN + 63) / 64;   // 313 gemm blocks

    k_wsplit<<<2048, 256>>>(preW, postW, mixW);
    k_embed<<<NN * 64 / 256, 256>>>(x, atom_emb);
    k_bond<<<1, 512>>>(bond_emb, preW, preB);
    tgemm<0, 128><<<dim3(GB, 2), 256, SMEM128>>>(p_AsH, p_AsL, KA, p_WsH, p_WsL, 256, nullptr,
                                                 p_P1, p_P2, nullptr, nullptr, NN, 128, nullptr);

    k_init_zero<<<(NN + 255) / 256, 256>>>();
    k_count<<<NE / 256, 256>>>(eidx + dst_off);
    k_scan<<<1, 1024>>>();
    k_nodeprep<<<(NN + 255) / 256, 256>>>();
    k_scatter<<<NE / 256, 256>>>(eidx + src_off, eidx + dst_off, eattr);

    for (int l = 0; l < NL; l++) {
        __nv_bfloat16* wH = p_WsH + (size_t)l * WL;
        __nv_bfloat16* wL = p_WsL + (size_t)l * WL;
        if (l > 0) {
            k_bond<<<1, 512>>>(bond_emb, preW + (size_t)l * 384 * DD, preB + l * DD);
            tgemm<0, 128><<<dim3(GB, 2), 256, SMEM128>>>(p_AsH, p_AsL, KA, wH, wL, 256, nullptr,
                                                         p_P1, p_P2, nullptr, nullptr,
                                                         NN, 128, nullptr);
        }
        k_edgeagg<<<NN / 8, 256>>>();
        tgemm<1, 64><<<dim3(GB, 2), 256, SMEM64>>>(p_AsH, p_AsL, KA,
                                                   wH + WOFF_POST, wL + WOFF_POST, 128,
                                                   postB + l * DD, nullptr, nullptr,
                                                   p_phsH, p_phsL, NN, 1664, nullptr);
        tgemm<2, 64><<<dim3(GB, 2), 256, SMEM64>>>(p_phsH, p_phsL, 128,
                                                   wH + WOFF_MIX, wL + WOFF_MIX, 128,
                                                   mixB + l * DD, p_phs, nullptr,
                                                   nullptr, nullptr, NN, 128, snorm);
        k_bnres<<<NN * 64 / 256, 256>>>(gamma + l * DD, beta + l * DD);
    }

    k_zero_pool<<<(NG * DD + 255) / 256, 256>>>();
    k_pool<<<NN * 32 / 256, 256>>>(batch);
    k_readout<<<NG, 64>>>(rW1, rb1, rW2, rb2, rW3, rb3, out);
}

// round 17
// speedup vs baseline: 1.0393x; 1.0393x over previous
#include <cuda_runtime.h>
#include <cuda_bf16.h>
#include <cstdint>
#include <math.h>

#define NN 20000
#define NE 320000
#define NG 256
#define DD 128
#define NL 4
#define AVG_LOG 2.8332133440562162f
#define EPSV 1e-5f
#define SLOPE 0.01f

#define KA 1664            // A row length (bf16) = h(128) + 3*4*128
#define WL 262144          // weight plane bf16 per layer
#define WOFF_POST 32768
#define WOFF_MIX 245760

// ---------------- scratch (static device memory; no allocation) ----------------
__device__ float g_h[NN * DD];
__device__ float g_P1[NN * DD];
__device__ float g_P2[NN * DD];
__device__ float g_phs[NN * DD];
__device__ float g_bond[4 * DD];
__device__ __nv_bfloat16 g_AsH[(size_t)NN * KA];
__device__ __nv_bfloat16 g_AsL[(size_t)NN * KA];
__device__ __nv_bfloat16 g_phsH[(size_t)NN * DD];
__device__ __nv_bfloat16 g_phsL[(size_t)NN * DD];
__device__ __nv_bfloat16 g_WsH[4 * WL];
__device__ __nv_bfloat16 g_WsL[4 * WL];
__device__ int   g_deg[NN];
__device__ int   g_off[NN + 1];
__device__ int   g_cur[NN];
__device__ int2  g_epack[NE];
__device__ float g_dinv[NN], g_amp[NN], g_att[NN];
__device__ float g_bnsum[DD], g_bnsq[DD];
__device__ float g_gsum[NG * DD];
__device__ float g_gcnt[NG];

// ---------------- helpers ----------------
__device__ __forceinline__ void splitp(float x, float y, __nv_bfloat162& h, __nv_bfloat162& l) {
    __nv_bfloat16 hx = __float2bfloat16_rn(x);
    __nv_bfloat16 hy = __float2bfloat16_rn(y);
    h.x = hx; h.y = hy;
    l.x = __float2bfloat16_rn(x - __bfloat162float(hx));
    l.y = __float2bfloat16_rn(y - __bfloat162float(hy));
}

__device__ __forceinline__ void mma_bf16(float c[4], const uint32_t a[4], const uint32_t b[2]) {
    asm volatile(
        "mma.sync.aligned.m16n8k16.row.col.f32.bf16.bf16.f32 "
        "{%0,%1,%2,%3}, {%4,%5,%6,%7}, {%8,%9}, {%0,%1,%2,%3};"
        : "+f"(c[0]), "+f"(c[1]), "+f"(c[2]), "+f"(c[3])
        : "r"(a[0]), "r"(a[1]), "r"(a[2]), "r"(a[3]), "r"(b[0]), "r"(b[1]));
}

__device__ __forceinline__ void cpa16(void* dst, const void* src, bool pred) {
    uint32_t d = (uint32_t)__cvta_generic_to_shared(dst);
    int sz = pred ? 16 : 0;
    asm volatile("cp.async.cg.shared.global [%0], [%1], 16, %2;" :: "r"(d), "l"(src), "r"(sz));
}

#define LDSM4(r, addr)                                                          \
    asm volatile("ldmatrix.sync.aligned.m8n8.x4.shared.b16 {%0,%1,%2,%3}, [%4];"\
        : "=r"((r)[0]), "=r"((r)[1]), "=r"((r)[2]), "=r"((r)[3]) : "r"(addr))

#define LDSM4T(r, addr)                                                         \
    asm volatile("ldmatrix.sync.aligned.m8n8.x4.trans.shared.b16 {%0,%1,%2,%3}, [%4];"\
        : "=r"((r)[0]), "=r"((r)[1]), "=r"((r)[2]), "=r"((r)[3]) : "r"(addr))

// ---------------- weight pre-split (once per launch) ----------------
__global__ void k_wsplit(const float* __restrict__ preW, const float* __restrict__ postW,
                         const float* __restrict__ mixW) {
    int idx2 = blockIdx.x * 256 + threadIdx.x;   // 0..524287 (element pairs)
    int l = idx2 >> 17;
    int rem2 = (idx2 & 131071) * 2;
    const float* src;
    if (rem2 < WOFF_POST) {
        int k = rem2 >> 8, n = rem2 & 255;
        src = preW + (size_t)l * 384 * 128 + (size_t)((n < 128 ? k : 128 + k)) * 128 + (n & 127);
    } else if (rem2 < WOFF_MIX) {
        int r2 = rem2 - WOFF_POST;
        src = postW + (size_t)l * 1664 * 128 + (size_t)(r2 >> 7) * 128 + (r2 & 127);
    } else {
        int r2 = rem2 - WOFF_MIX;
        src = mixW + (size_t)l * 128 * 128 + (size_t)(r2 >> 7) * 128 + (r2 & 127);
    }
    float a = src[0], b = src[1];
    __nv_bfloat162 h, lo;
    splitp(a, b, h, lo);
    *(__nv_bfloat162*)&g_WsH[(size_t)l * WL + rem2] = h;
    *(__nv_bfloat162*)&g_WsL[(size_t)l * WL + rem2] = lo;
}

// ---------------- setup kernels ----------------
__global__ void k_init_zero() {
    int i = blockIdx.x * blockDim.x + threadIdx.x;
    if (i < NN) { g_deg[i] = 0; g_cur[i] = 0; }
}

__global__ void k_count(const int* __restrict__ dst) {
    int e = blockIdx.x * blockDim.x + threadIdx.x;
    if (e < NE) atomicAdd(&g_deg[dst[e]], 1);
}

__global__ void k_scan() {
    __shared__ int s[1024];
    __shared__ int run;
    int t = threadIdx.x;
    if (t == 0) run = 0;
    for (int base = 0; base < NN; base += 1024) {
        __syncthreads();
        int r = run;
        int v = (base + t < NN) ? g_deg[base + t] : 0;
        s[t] = v;
        __syncthreads();
        for (int d2 = 1; d2 < 1024; d2 <<= 1) {
            int tv = (t >= d2) ? s[t - d2] : 0;
            __syncthreads();
            s[t] += tv;
            __syncthreads();
        }
        if (base + t < NN) g_off[base + t] = r + s[t] - v;
        if (t == 0) run = r + s[1023];
    }
    __syncthreads();
    if (t == 0) g_off[NN] = run;
}

__global__ void k_nodeprep() {
    int n = blockIdx.x * blockDim.x + threadIdx.x;
    if (n >= NN) return;
    float d = (float)g_deg[n];
    g_dinv[n] = 1.0f / fmaxf(d, 1.0f);
    float logd = log1pf(d);
    g_amp[n] = logd / AVG_LOG;
    g_att[n] = AVG_LOG / fmaxf(logd, EPSV);
}

__global__ void k_scatter(const int* __restrict__ src, const int* __restrict__ dst,
                          const int* __restrict__ attr) {
    int e = blockIdx.x * blockDim.x + threadIdx.x;
    if (e >= NE) return;
    int d = dst[e];
    int pos = g_off[d] + atomicAdd(&g_cur[d], 1);
    g_epack[pos] = make_int2(src[e], attr[e]);
}

__global__ void k_embed(const int* __restrict__ x, const float* __restrict__ atom_emb) {
    int idx = blockIdx.x * blockDim.x + threadIdx.x;
    if (idx >= NN * 64) return;
    int n = idx >> 6, c = (idx & 63) * 2;
    const float* e = &atom_emb[x[n] * DD];
    float a = e[c], b = e[c + 1];
    g_h[n * DD + c] = a;
    g_h[n * DD + c + 1] = b;
    __nv_bfloat162 h, lo;
    splitp(a, b, h, lo);
    *(__nv_bfloat162*)&g_AsH[(size_t)n * KA + c] = h;
    *(__nv_bfloat162*)&g_AsL[(size_t)n * KA + c] = lo;
}

__global__ void k_bond(const float* __restrict__ bond_emb, const float* __restrict__ preWl,
                       const float* __restrict__ preBl) {
    int t = threadIdx.x;            // 512 threads
    if (t < DD) { g_bnsum[t] = 0.f; g_bnsq[t] = 0.f; }
    int b = t >> 7, c = t & 127;
    float a = preBl[c];
    for (int k = 0; k < DD; k++)
        a += bond_emb[b * DD + k] * preWl[(256 + k) * DD + c];
    g_bond[t] = a;
}

// ---------------- bf16-split GEMM: ldmatrix + 2-stage cp.async, BK=64 ----------------
// C[M,128] = epi(A[M,K] @ B[K,128]); A,B as hi/lo bf16 planes.
// grid.y selects B n-half (fused pre: ldb=256, y=0->C, y=1->C2).
// EPI 0: fp32. EPI 1: +bias leaky -> split planes. EPI 2: +bias leaky *snorm -> fp32 + BN sums.
// BM=64, BN=128, BK=64. 8 warps (2x4), warp tile 32x32. 2 CTAs/SM.

#define APITCH 72
#define BPITCH 136
#define SA_PL (64 * APITCH)          // 4608 bf16 per plane
#define SB_PL (64 * BPITCH)          // 8704 bf16 per plane
#define STG (2 * SA_PL + 2 * SB_PL)  // 26624 bf16 per stage
#define SMEM128 (2 * STG * 2)        // 106496 bytes

template <int EPI>
__global__ void __launch_bounds__(256, 2) tgemm(const __nv_bfloat16* __restrict__ AH,
                                                const __nv_bfloat16* __restrict__ AL, int lda,
                                                const __nv_bfloat16* __restrict__ BH,
                                                const __nv_bfloat16* __restrict__ BL, int ldb,
                                                const float* __restrict__ bias,
                                                float* __restrict__ C, float* __restrict__ C2,
                                                __nv_bfloat16* __restrict__ CsH,
                                                __nv_bfloat16* __restrict__ CsL,
                                                int M, int K,
                                                const float* __restrict__ snorm) {
    extern __shared__ __nv_bfloat16 sm[];
    __shared__ float bnS[128], bnQ[128];

    int tid = threadIdx.x;
    int lane = tid & 31, wid = tid >> 5;
    int wm = wid & 1, wn = wid >> 1;
    int g = lane >> 2, tg = lane & 3;
    int mat = lane >> 3, l8 = lane & 7;
    int m0 = wm * 32, n0 = wn * 32;
    int row0 = blockIdx.x * 64;
    int bcol = blockIdx.y * 128;
    float* Cout = blockIdx.y ? C2 : C;

    if (EPI == 2 && tid < 128) { bnS[tid] = 0.f; bnQ[tid] = 0.f; }

    float acc[2][4][4];
#pragma unroll
    for (int i = 0; i < 2; i++)
#pragma unroll
        for (int j = 0; j < 4; j++)
#pragma unroll
            for (int q = 0; q < 4; q++) acc[i][j][q] = 0.f;

    // A tile: 2 planes x 64 rows x 64 k = 1024 cpa16; B tile: 2 planes x 64 k x 128 n = 2048 cpa16
#define COPY_TILE(K0, BUF)                                                      \
    {                                                                           \
        __nv_bfloat16* stg = sm + (BUF) * STG;                                  \
        _Pragma("unroll")                                                       \
        for (int i = 0; i < 4; i++) {                                           \
            int j = tid + i * 256;                                              \
            int p = j >> 9, r2 = j & 511;                                       \
            int row = r2 >> 3, ch = (r2 & 7) * 8;                               \
            int gr = row0 + row;                                                \
            int gc = gr < M ? gr : M - 1;                                       \
            const __nv_bfloat16* s = (p ? AL : AH) + (size_t)gc * lda + (K0) + ch; \
            cpa16(stg + p * SA_PL + row * APITCH + ch, s, gr < M);              \
        }                                                                       \
        _Pragma("unroll")                                                       \
        for (int i = 0; i < 8; i++) {                                           \
            int j = tid + i * 256;                                              \
            int p = j >> 10, r2 = j & 1023;                                     \
            int kr = r2 >> 4, ch = (r2 & 15) * 8;                               \
            const __nv_bfloat16* s = (p ? BL : BH) + (size_t)((K0) + kr) * ldb + bcol + ch; \
            cpa16(stg + 2 * SA_PL + p * SB_PL + kr * BPITCH + ch, s, true);     \
        }                                                                       \
        asm volatile("cp.async.commit_group;");                                 \
    }

    int T = K >> 6;           // 64-k tiles
    COPY_TILE(0, 0);

    int buf = 0;
    for (int t = 0; t < T; t++) {
        asm volatile("cp.async.wait_group 0;");
        __syncthreads();
        if (t + 1 < T) COPY_TILE((t + 1) * 64, buf ^ 1);

        __nv_bfloat16* sAH = sm + buf * STG;
        __nv_bfloat16* sAL = sAH + SA_PL;
        __nv_bfloat16* sBH = sAH + 2 * SA_PL;
        __nv_bfloat16* sBL = sBH + SB_PL;
        buf ^= 1;

#pragma unroll
        for (int ks = 0; ks < 4; ks++) {
            int kb = ks * 16;
            uint32_t ah[2][4], al[2][4], bh[2][4], bl[2][4];
#pragma unroll
            for (int mf = 0; mf < 2; mf++) {
                int off = (m0 + mf * 16 + (mat & 1) * 8 + l8) * APITCH + kb + (mat >> 1) * 8;
                uint32_t aH = (uint32_t)__cvta_generic_to_shared(sAH + off);
                uint32_t aL = (uint32_t)__cvta_generic_to_shared(sAL + off);
                LDSM4(ah[mf], aH);
                LDSM4(al[mf], aL);
            }
#pragma unroll
            for (int np = 0; np < 2; np++) {
                int off = (kb + (mat & 1) * 8 + l8) * BPITCH + n0 + np * 16 + (mat >> 1) * 8;
                uint32_t bHa = (uint32_t)__cvta_generic_to_shared(sBH + off);
                uint32_t bLa = (uint32_t)__cvta_generic_to_shared(sBL + off);
                LDSM4T(bh[np], bHa);
                LDSM4T(bl[np], bLa);
            }
#pragma unroll
            for (int mf = 0; mf < 2; mf++)
#pragma unroll
                for (int nf = 0; nf < 4; nf++) {
                    uint32_t bhf[2] = {bh[nf >> 1][(nf & 1) * 2], bh[nf >> 1][(nf & 1) * 2 + 1]};
                    uint32_t blf[2] = {bl[nf >> 1][(nf & 1) * 2], bl[nf >> 1][(nf & 1) * 2 + 1]};
                    mma_bf16(acc[mf][nf], ah[mf], bhf);
                    mma_bf16(acc[mf][nf], ah[mf], blf);
                    mma_bf16(acc[mf][nf], al[mf], bhf);
                }
        }
        __syncthreads();
    }

    // ---- epilogue ----
#pragma unroll
    for (int mf = 0; mf < 2; mf++) {
        int r0 = row0 + m0 + mf * 16 + g;
        int r1 = r0 + 8;
        float sn0 = 1.f, sn1 = 1.f;
        if (EPI == 2) {
            if (r0 < M) sn0 = snorm[r0];
            if (r1 < M) sn1 = snorm[r1];
        }
#pragma unroll
        for (int nf = 0; nf < 4; nf++) {
            int col = n0 + nf * 8 + 2 * tg;
            float b0 = 0.f, b1 = 0.f;
            if (EPI >= 1) { b0 = bias[col]; b1 = bias[col + 1]; }
            float v0 = acc[mf][nf][0], v1 = acc[mf][nf][1];
            float v2 = acc[mf][nf][2], v3 = acc[mf][nf][3];
            if (EPI >= 1) {
                v0 += b0; v0 = v0 > 0.f ? v0 : SLOPE * v0;
                v1 += b1; v1 = v1 > 0.f ? v1 : SLOPE * v1;
                v2 += b0; v2 = v2 > 0.f ? v2 : SLOPE * v2;
                v3 += b1; v3 = v3 > 0.f ? v3 : SLOPE * v3;
            }
            if (EPI == 1) {
                __nv_bfloat162 h, lo;
                if (r0 < M) {
                    splitp(v0, v1, h, lo);
                    *(__nv_bfloat162*)&CsH[(size_t)r0 * DD + col] = h;
                    *(__nv_bfloat162*)&CsL[(size_t)r0 * DD + col] = lo;
                }
                if (r1 < M) {
                    splitp(v2, v3, h, lo);
                    *(__nv_bfloat162*)&CsH[(size_t)r1 * DD + col] = h;
                    *(__nv_bfloat162*)&CsL[(size_t)r1 * DD + col] = lo;
                }
            } else {
                if (EPI == 2) { v0 *= sn0; v1 *= sn0; v2 *= sn1; v3 *= sn1; }
                if (r0 < M) *(float2*)&Cout[(size_t)r0 * DD + col] = make_float2(v0, v1);
                if (r1 < M) *(float2*)&Cout[(size_t)r1 * DD + col] = make_float2(v2, v3);
                if (EPI == 2) {
                    float a0 = (r0 < M) ? v0 : 0.f, a1 = (r0 < M) ? v1 : 0.f;
                    float a2 = (r1 < M) ? v2 : 0.f, a3 = (r1 < M) ? v3 : 0.f;
                    float s0 = a0 + a2, s1 = a1 + a3;
                    float q0 = a0 * a0 + a2 * a2, q1 = a1 * a1 + a3 * a3;
#pragma unroll
                    for (int o = 4; o <= 16; o <<= 1) {
                        s0 += __shfl_down_sync(0xffffffffu, s0, o);
                        s1 += __shfl_down_sync(0xffffffffu, s1, o);
                        q0 += __shfl_down_sync(0xffffffffu, q0, o);
                        q1 += __shfl_down_sync(0xffffffffu, q1, o);
                    }
                    if (lane < 4) {
                        atomicAdd(&bnS[col], s0);
                        atomicAdd(&bnS[col + 1], s1);
                        atomicAdd(&bnQ[col], q0);
                        atomicAdd(&bnQ[col + 1], q1);
                    }
                }
            }
        }
    }
    if (EPI == 2) {
        __syncthreads();
        if (tid < 128) {
            atomicAdd(&g_bnsum[tid], bnS[tid]);
            atomicAdd(&g_bnsq[tid], bnQ[tid]);
        }
    }
}

// ---------------- edge aggregation (CSR, atomic-free, MLP=4) ----------------
__global__ void k_edgeagg() {
    __shared__ __align__(16) float sb[4 * DD];
    int tid = threadIdx.x;
    for (int i = tid; i < 4 * DD; i += blockDim.x) sb[i] = g_bond[i];
    __syncthreads();
    int w = (blockIdx.x * blockDim.x + tid) >> 5;
    int lane = tid & 31;
    int c0 = lane * 4;
    float4 base = *(float4*)&g_P1[w * DD + c0];
    int off = g_off[w], deg = g_deg[w];
    float s0 = 0, s1 = 0, s2 = 0, s3 = 0;
    float q0 = 0, q1 = 0, q2 = 0, q3 = 0;
    float x0 = -3.4e38f, x1 = -3.4e38f, x2 = -3.4e38f, x3 = -3.4e38f;
    float n0 = 3.4e38f, n1 = 3.4e38f, n2 = 3.4e38f, n3 = 3.4e38f;

#define EPROC(p, bb)                                                            \
    {                                                                           \
        float m0 = base.x + (p).x + (bb).x; m0 = m0 > 0 ? m0 : SLOPE * m0;      \
        float m1 = base.y + (p).y + (bb).y; m1 = m1 > 0 ? m1 : SLOPE * m1;      \
        float m2 = base.z + (p).z + (bb).z; m2 = m2 > 0 ? m2 : SLOPE * m2;      \
        float m3 = base.w + (p).w + (bb).w; m3 = m3 > 0 ? m3 : SLOPE * m3;      \
        s0 += m0; s1 += m1; s2 += m2; s3 += m3;                                 \
        q0 += m0 * m0; q1 += m1 * m1; q2 += m2 * m2; q3 += m3 * m3;             \
        x0 = fmaxf(x0, m0); x1 = fmaxf(x1, m1);                                 \
        x2 = fmaxf(x2, m2); x3 = fmaxf(x3, m3);                                 \
        n0 = fminf(n0, m0); n1 = fminf(n1, m1);                                 \
        n2 = fminf(n2, m2); n3 = fminf(n3, m3);                                 \
    }

    int i = 0;
    for (; i + 4 <= deg; i += 4) {
        int e = off + i;
        int2 e0 = g_epack[e], e1 = g_epack[e + 1], e2 = g_epack[e + 2], e3 = g_epack[e + 3];
        float4 p0 = *(float4*)&g_P2[e0.x * DD + c0];
        float4 p1 = *(float4*)&g_P2[e1.x * DD + c0];
        float4 p2 = *(float4*)&g_P2[e2.x * DD + c0];
        float4 p3 = *(float4*)&g_P2[e3.x * DD + c0];
        float4 b0 = *(float4*)&sb[e0.y * DD + c0];
        float4 b1 = *(float4*)&sb[e1.y * DD + c0];
        float4 b2 = *(float4*)&sb[e2.y * DD + c0];
        float4 b3 = *(float4*)&sb[e3.y * DD + c0];
        EPROC(p0, b0); EPROC(p1, b1); EPROC(p2, b2); EPROC(p3, b3);
    }
    for (; i < deg; i++) {
        int2 ep = g_epack[off + i];
        float4 p = *(float4*)&g_P2[ep.x * DD + c0];
        float4 bb = *(float4*)&sb[ep.y * DD + c0];
        EPROC(p, bb);
    }
#undef EPROC

    float dinv = g_dinv[w];
    bool nb = deg > 0;
    float me0 = s0 * dinv, me1 = s1 * dinv, me2 = s2 * dinv, me3 = s3 * dinv;
    float sd0 = nb ? sqrtf(fmaxf(q0 * dinv - me0 * me0, 0.f) + EPSV) : 0.f;
    float sd1 = nb ? sqrtf(fmaxf(q1 * dinv - me1 * me1, 0.f) + EPSV) : 0.f;
    float sd2 = nb ? sqrtf(fmaxf(q2 * dinv - me2 * me2, 0.f) + EPSV) : 0.f;
    float sd3 = nb ? sqrtf(fmaxf(q3 * dinv - me3 * me3, 0.f) + EPSV) : 0.f;
    if (!nb) { x0 = x1 = x2 = x3 = 0.f; n0 = n1 = n2 = n3 = 0.f; }

    float vs[4][4] = {{me0, me1, me2, me3}, {x0, x1, x2, x3},
                      {n0, n1, n2, n3}, {sd0, sd1, sd2, sd3}};
    float amp = g_amp[w], att = g_att[w];
    float scs[3] = {1.f, amp, att};
#pragma unroll
    for (int v = 0; v < 3; v++) {
        float sc = scs[v];
#pragma unroll
        for (int s = 0; s < 4; s++) {
            size_t k = (size_t)w * KA + 128 + v * 512 + s * 128 + c0;
            __nv_bfloat162 h, lo;
            splitp(sc * vs[s][0], sc * vs[s][1], h, lo);
            *(__nv_bfloat162*)&g_AsH[k] = h;
            *(__nv_bfloat162*)&g_AsL[k] = lo;
            splitp(sc * vs[s][2], sc * vs[s][3], h, lo);
            *(__nv_bfloat162*)&g_AsH[k + 2] = h;
            *(__nv_bfloat162*)&g_AsL[k + 2] = lo;
        }
    }
}

// ---------------- batchnorm residual ----------------
__global__ void k_bnres(const float* __restrict__ gamma, const float* __restrict__ beta) {
    int idx = blockIdx.x * blockDim.x + threadIdx.x;
    if (idx >= NN * 64) return;
    int n = idx >> 6, c = (idx & 63) * 2;
    float mu0 = g_bnsum[c] * (1.0f / NN);
    float var0 = g_bnsq[c] * (1.0f / NN) - mu0 * mu0;
    float mu1 = g_bnsum[c + 1] * (1.0f / NN);
    float var1 = g_bnsq[c + 1] * (1.0f / NN) - mu1 * mu1;
    float p0 = g_phs[n * DD + c], p1 = g_phs[n * DD + c + 1];
    float h0 = g_h[n * DD + c] + gamma[c] * (p0 - mu0) * rsqrtf(var0 + EPSV) + beta[c];
    float h1 = g_h[n * DD + c + 1] + gamma[c + 1] * (p1 - mu1) * rsqrtf(var1 + EPSV) + beta[c + 1];
    g_h[n * DD + c] = h0;
    g_h[n * DD + c + 1] = h1;
    __nv_bfloat162 h, lo;
    splitp(h0, h1, h, lo);
    *(__nv_bfloat162*)&g_AsH[(size_t)n * KA + c] = h;
    *(__nv_bfloat162*)&g_AsL[(size_t)n * KA + c] = lo;
}

// ---------------- pooling + readout ----------------
__global__ void k_zero_pool() {
    int i = blockIdx.x * blockDim.x + threadIdx.x;
    if (i < NG * DD) g_gsum[i] = 0.f;
    if (i < NG) g_gcnt[i] = 0.f;
}

__global__ void k_pool(const int* __restrict__ batch) {
    int idx = blockIdx.x * blockDim.x + threadIdx.x;
    if (idx >= NN * 32) return;
    int n = idx >> 5, q = idx & 31;
    int b = batch[n];
    float4 v = *(float4*)&g_h[n * DD + q * 4];
    atomicAdd(&g_gsum[b * DD + q * 4 + 0], v.x);
    atomicAdd(&g_gsum[b * DD + q * 4 + 1], v.y);
    atomicAdd(&g_gsum[b * DD + q * 4 + 2], v.z);
    atomicAdd(&g_gsum[b * DD + q * 4 + 3], v.w);
    if (q == 0) atomicAdd(&g_gcnt[b], 1.f);
}

__global__ void k_readout(const float* __restrict__ rW1, const float* __restrict__ rb1,
                          const float* __restrict__ rW2, const float* __restrict__ rb2,
                          const float* __restrict__ rW3, const float* __restrict__ rb3,
                          float* __restrict__ out) {
    __shared__ float sg[128], s1[64], s2[32];
    int b = blockIdx.x, t = threadIdx.x;   // 64 threads
    float cnt = fmaxf(g_gcnt[b], 1.f);
    for (int i = t; i < 128; i += 64) sg[i] = g_gsum[b * DD + i] / cnt;
    __syncthreads();
    float a = 0.f;
    for (int k = 0; k < 128; k++) a += sg[k] * rW1[k * 64 + t];
    s1[t] = fmaxf(a + rb1[t], 0.f);
    __syncthreads();
    if (t < 32) {
        float a2 = 0.f;
        for (int k = 0; k < 64; k++) a2 += s1[k] * rW2[k * 32 + t];
        s2[t] = fmaxf(a2 + rb2[t], 0.f);
    }
    __syncthreads();
    if (t < 32) {
        float p = s2[t] * rW3[t];
#pragma unroll
        for (int o = 16; o; o >>= 1) p += __shfl_down_sync(0xffffffffu, p, o);
        if (t == 0) out[b] = p + rb3[0];
    }
}

// ---------------- host launcher ----------------
static void* symp(const void* sym) {
    void* p = nullptr;
    cudaGetSymbolAddress(&p, sym);
    return p;
}

extern "C" void kernel_launch(void* const* d_in, const int* in_sizes, int n_in,
                              void* d_out, int out_size) {
    const int* x = (const int*)d_in[0];
    const int* batch = (const int*)d_in[1];
    const int* eidx = (const int*)d_in[2];    // [2,E]: src then dst
    const float* snorm = (const float*)d_in[3];
    const int* eattr = (const int*)d_in[4];
    const float* atom_emb = (const float*)d_in[5];
    const float* bond_emb = (const float*)d_in[6];
    const float* preW = (const float*)d_in[7];
    const float* preB = (const float*)d_in[8];
    const float* postW = (const float*)d_in[9];
    const float* postB = (const float*)d_in[10];
    const float* mixW = (const float*)d_in[11];
    const float* mixB = (const float*)d_in[12];
    const float* gamma = (const float*)d_in[13];
    const float* beta = (const float*)d_in[14];
    const float* rW1 = (const float*)d_in[15];
    const float* rb1 = (const float*)d_in[16];
    const float* rW2 = (const float*)d_in[17];
    const float* rb2 = (const float*)d_in[18];
    const float* rW3 = (const float*)d_in[19];
    const float* rb3 = (const float*)d_in[20];
    float* out = (float*)d_out;

    float* p_P1 = (float*)symp(g_P1);
    float* p_P2 = (float*)symp(g_P2);
    float* p_phs = (float*)symp(g_phs);
    __nv_bfloat16* p_AsH = (__nv_bfloat16*)symp(g_AsH);
    __nv_bfloat16* p_AsL = (__nv_bfloat16*)symp(g_AsL);
    __nv_bfloat16* p_phsH = (__nv_bfloat16*)symp(g_phsH);
    __nv_bfloat16* p_phsL = (__nv_bfloat16*)symp(g_phsL);
    __nv_bfloat16* p_WsH = (__nv_bfloat16*)symp(g_WsH);
    __nv_bfloat16* p_WsL = (__nv_bfloat16*)symp(g_WsL);

    cudaFuncSetAttribute(tgemm<0>, cudaFuncAttributeMaxDynamicSharedMemorySize, SMEM128);
    cudaFuncSetAttribute(tgemm<1>, cudaFuncAttributeMaxDynamicSharedMemorySize, SMEM128);
    cudaFuncSetAttribute(tgemm<2>, cudaFuncAttributeMaxDynamicSharedMemorySize, SMEM128);

    const int src_off = 0, dst_off = NE;
    const int GB = (NN + 63) / 64;   // 313 gemm blocks

    k_wsplit<<<2048, 256>>>(preW, postW, mixW);
    k_embed<<<NN * 64 / 256, 256>>>(x, atom_emb);
    k_bond<<<1, 512>>>(bond_emb, preW, preB);
    tgemm<0><<<dim3(GB, 2), 256, SMEM128>>>(p_AsH, p_AsL, KA, p_WsH, p_WsL, 256, nullptr,
                                            p_P1, p_P2, nullptr, nullptr, NN, 128, nullptr);

    k_init_zero<<<(NN + 255) / 256, 256>>>();
    k_count<<<NE / 256, 256>>>(eidx + dst_off);
    k_scan<<<1, 1024>>>();
    k_nodeprep<<<(NN + 255) / 256, 256>>>();
    k_scatter<<<NE / 256, 256>>>(eidx + src_off, eidx + dst_off, eattr);

    for (int l = 0; l < NL; l++) {
        __nv_bfloat16* wH = p_WsH + (size_t)l * WL;
        __nv_bfloat16* wL = p_WsL + (size_t)l * WL;
        if (l > 0) {
            k_bond<<<1, 512>>>(bond_emb, preW + (size_t)l * 384 * DD, preB + l * DD);
            tgemm<0><<<dim3(GB, 2), 256, SMEM128>>>(p_AsH, p_AsL, KA, wH, wL, 256, nullptr,
                                                    p_P1, p_P2, nullptr, nullptr, NN, 128, nullptr);
        }
        k_edgeagg<<<NN / 8, 256>>>();
        tgemm<1><<<GB, 256, SMEM128>>>(p_AsH, p_AsL, KA, wH + WOFF_POST, wL + WOFF_POST, 128,
                                       postB + l * DD, nullptr, nullptr, p_phsH, p_phsL,
                                       NN, 1664, nullptr);
        tgemm<2><<<GB, 256, SMEM128>>>(p_phsH, p_phsL, 128, wH + WOFF_MIX, wL + WOFF_MIX, 128,
                                       mixB + l * DD, p_phs, nullptr, nullptr, nullptr,
                                       NN, 128, snorm);
        k_bnres<<<NN * 64 / 256, 256>>>(gamma + l * DD, beta + l * DD);
    }

    k_zero_pool<<<(NG * DD + 255) / 256, 256>>>();
    k_pool<<<NN * 32 / 256, 256>>>(batch);
    k_readout<<<NG, 64>>>(rW1, rb1, rW2, rb2, rW3, rb3, out);
}